// round 15
// baseline (speedup 1.0000x reference)
#include <cuda_runtime.h>
#include <cuda_fp16.h>
#include <cuda_bf16.h>
#include <cstdint>

// Problem constants (fixed by the dataset)
#define N_NODES_MAX 50048
#define N_EDGES_MAX 800000
#define IN_FEATS    128
#define NUM_HEADS   4
#define OUT_FEATS   32
#define HD          (NUM_HEADS * OUT_FEATS)   // 128

#define SCAN_B 1024
#define MAX_BLOCKS ((N_NODES_MAX + SCAN_B - 1) / SCAN_B + 2)

// Scratch (static __device__ arrays; no allocation allowed)
__device__ float   g_ft [N_NODES_MAX * HD];   // projected features fp32 [N,128]
__device__ __half2 g_fth[N_NODES_MAX * 64];   // same rows as half2 (gather mirror)
__device__ int     g_cnt[N_NODES_MAX];        // in-degree histogram
__device__ int     g_off[N_NODES_MAX];        // CSR row starts
__device__ int     g_cur[N_NODES_MAX];        // scatter cursors
__device__ int     g_bsum[MAX_BLOCKS];        // per-block sums for scan
__device__ int     g_csr_src[N_EDGES_MAX];    // src node per CSR slot

// ---------------------------------------------------------------------------
// K1: in-degree histogram
// ---------------------------------------------------------------------------
__global__ void hist_kernel(const int* __restrict__ dst, int E) {
    int i = blockIdx.x * blockDim.x + threadIdx.x;
    if (i < E) atomicAdd(&g_cnt[dst[i]], 1);
}

// ---------------------------------------------------------------------------
// K2a: per-block sums for the scan
// ---------------------------------------------------------------------------
__global__ void scan_phase1(int N) {
    int i = blockIdx.x * SCAN_B + threadIdx.x;
    int v = (i < N) ? g_cnt[i] : 0;
    #pragma unroll
    for (int o = 16; o > 0; o >>= 1) v += __shfl_xor_sync(0xffffffffu, v, o);
    __shared__ int wsum[32];
    int lane = threadIdx.x & 31, w = threadIdx.x >> 5;
    if (lane == 0) wsum[w] = v;
    __syncthreads();
    if (w == 0) {
        int x = wsum[lane];
        #pragma unroll
        for (int o = 16; o > 0; o >>= 1) x += __shfl_xor_sync(0xffffffffu, x, o);
        if (lane == 0) g_bsum[blockIdx.x] = x;
    }
}

// ---------------------------------------------------------------------------
// K2b: per-block scan with inter-block base folded in (warp 0 sums g_bsum).
// ---------------------------------------------------------------------------
__global__ void scan_phase3(int N) {
    __shared__ int base_off;
    int lane = threadIdx.x & 31, w = threadIdx.x >> 5;
    if (threadIdx.x < 32) {
        int acc = 0;
        for (int j = lane; j < (int)blockIdx.x; j += 32) acc += g_bsum[j];
        #pragma unroll
        for (int o = 16; o > 0; o >>= 1) acc += __shfl_xor_sync(0xffffffffu, acc, o);
        if (lane == 0) base_off = acc;
    }
    int i = blockIdx.x * SCAN_B + threadIdx.x;
    int v = (i < N) ? g_cnt[i] : 0;
    int x = v;
    #pragma unroll
    for (int o = 1; o < 32; o <<= 1) {
        int y = __shfl_up_sync(0xffffffffu, x, o);
        if (lane >= o) x += y;
    }
    __shared__ int woff[32];
    if (lane == 31) woff[w] = x;
    __syncthreads();
    if (w == 0) {
        int y = woff[lane];
        int z = y;
        #pragma unroll
        for (int o = 1; o < 32; o <<= 1) {
            int t2 = __shfl_up_sync(0xffffffffu, z, o);
            if (lane >= o) z += t2;
        }
        woff[lane] = z - y;
    }
    __syncthreads();
    int excl = (x - v) + woff[w] + base_off;
    if (i < N) { g_off[i] = excl; g_cur[i] = excl; }
}

// ---------------------------------------------------------------------------
// K3: scatter src ids into CSR slots
// ---------------------------------------------------------------------------
__global__ void scatter_kernel(const int* __restrict__ src,
                               const int* __restrict__ dst, int E) {
    int i = blockIdx.x * blockDim.x + threadIdx.x;
    if (i < E) {
        int pos = atomicAdd(&g_cur[dst[i]], 1);
        g_csr_src[pos] = src[i];
    }
}

// ---------------------------------------------------------------------------
// K4: projection GEMM — R8 exact shape (measured best; do not reshape).
// 128x128 tile, BK=16, 256 threads, occ 2, 8x8 microtile as f32x2 pairs.
// Epilogue also emits fp16 mirror rows (g_fth) for the agg gather.
// Runs on a forked stream, concurrent with the CSR build.
// ---------------------------------------------------------------------------
#define GM 128
#define GK 16
__global__ void __launch_bounds__(256, 2)
gemm_kernel(const float* __restrict__ feat,
            const float* __restrict__ W,
            int N) {
    __shared__ float As[GK][GM];    // feat tile, transposed: As[k][r]   8KB
    __shared__ float Bs[GK][HD];    // W tile, transposed:    Bs[k][o]   8KB

    const int tid = threadIdx.x;           // 0..255
    const int tx  = tid & 15;              // col group: cols tx*8..tx*8+7
    const int ty  = tid >> 4;              // row group: rows ty*8..ty*8+7
    const int row0 = blockIdx.x * GM;

    const int rA0 = (tid + 0)   >> 2, kq0 = (tid + 0)   & 3;
    const int rA1 = (tid + 256) >> 2, kq1 = (tid + 256) & 3;

    unsigned long long acc[8][4];   // 8 rows x 4 f32x2 pairs (= 8 cols)
    #pragma unroll
    for (int i = 0; i < 8; i++)
        #pragma unroll
        for (int j = 0; j < 4; j++) acc[i][j] = 0ULL;

    float4 fa0, fa1, fw0, fw1;
    {
        fa0 = make_float4(0.f, 0.f, 0.f, 0.f);
        fa1 = fa0;
        if (row0 + rA0 < N) fa0 = *(const float4*)&feat[(size_t)(row0 + rA0) * IN_FEATS + (kq0 << 2)];
        if (row0 + rA1 < N) fa1 = *(const float4*)&feat[(size_t)(row0 + rA1) * IN_FEATS + (kq1 << 2)];
        fw0 = *(const float4*)&W[(size_t)rA0 * IN_FEATS + (kq0 << 2)];
        fw1 = *(const float4*)&W[(size_t)rA1 * IN_FEATS + (kq1 << 2)];
    }

    #pragma unroll 1
    for (int kb = 0; kb < IN_FEATS / GK; kb++) {
        As[(kq0 << 2) + 0][rA0] = fa0.x; As[(kq0 << 2) + 1][rA0] = fa0.y;
        As[(kq0 << 2) + 2][rA0] = fa0.z; As[(kq0 << 2) + 3][rA0] = fa0.w;
        As[(kq1 << 2) + 0][rA1] = fa1.x; As[(kq1 << 2) + 1][rA1] = fa1.y;
        As[(kq1 << 2) + 2][rA1] = fa1.z; As[(kq1 << 2) + 3][rA1] = fa1.w;
        Bs[(kq0 << 2) + 0][rA0] = fw0.x; Bs[(kq0 << 2) + 1][rA0] = fw0.y;
        Bs[(kq0 << 2) + 2][rA0] = fw0.z; Bs[(kq0 << 2) + 3][rA0] = fw0.w;
        Bs[(kq1 << 2) + 0][rA1] = fw1.x; Bs[(kq1 << 2) + 1][rA1] = fw1.y;
        Bs[(kq1 << 2) + 2][rA1] = fw1.z; Bs[(kq1 << 2) + 3][rA1] = fw1.w;
        __syncthreads();

        if (kb + 1 < IN_FEATS / GK) {
            int kc = (kb + 1) * GK;
            fa0 = make_float4(0.f, 0.f, 0.f, 0.f);
            fa1 = fa0;
            if (row0 + rA0 < N) fa0 = *(const float4*)&feat[(size_t)(row0 + rA0) * IN_FEATS + kc + (kq0 << 2)];
            if (row0 + rA1 < N) fa1 = *(const float4*)&feat[(size_t)(row0 + rA1) * IN_FEATS + kc + (kq1 << 2)];
            fw0 = *(const float4*)&W[(size_t)rA0 * IN_FEATS + kc + (kq0 << 2)];
            fw1 = *(const float4*)&W[(size_t)rA1 * IN_FEATS + kc + (kq1 << 2)];
        }

        #pragma unroll
        for (int k = 0; k < GK; k++) {
            float4 a0 = *(const float4*)&As[k][(ty << 3) + 0];
            float4 a1 = *(const float4*)&As[k][(ty << 3) + 4];
            float4 b0 = *(const float4*)&Bs[k][(tx << 3) + 0];
            float4 b1 = *(const float4*)&Bs[k][(tx << 3) + 4];
            unsigned long long bp[4];
            asm("mov.b64 %0, {%1, %2};" : "=l"(bp[0]) : "f"(b0.x), "f"(b0.y));
            asm("mov.b64 %0, {%1, %2};" : "=l"(bp[1]) : "f"(b0.z), "f"(b0.w));
            asm("mov.b64 %0, {%1, %2};" : "=l"(bp[2]) : "f"(b1.x), "f"(b1.y));
            asm("mov.b64 %0, {%1, %2};" : "=l"(bp[3]) : "f"(b1.z), "f"(b1.w));
            float av[8] = {a0.x, a0.y, a0.z, a0.w, a1.x, a1.y, a1.z, a1.w};
            #pragma unroll
            for (int i = 0; i < 8; i++) {
                unsigned long long ap;
                asm("mov.b64 %0, {%1, %1};" : "=l"(ap) : "f"(av[i]));
                #pragma unroll
                for (int jp = 0; jp < 4; jp++)
                    asm("fma.rn.f32x2 %0, %1, %2, %0;"
                        : "+l"(acc[i][jp]) : "l"(ap), "l"(bp[jp]));
            }
        }
        __syncthreads();
    }

    #pragma unroll
    for (int i = 0; i < 8; i++) {
        int r = row0 + (ty << 3) + i;
        if (r < N) {
            unsigned long long* d =
                (unsigned long long*)&g_ft[(size_t)r * HD + (tx << 3)];
            ulonglong2 v0; v0.x = acc[i][0]; v0.y = acc[i][1];
            ulonglong2 v1; v1.x = acc[i][2]; v1.y = acc[i][3];
            *(ulonglong2*)(d + 0) = v0;
            *(ulonglong2*)(d + 2) = v1;

            __half2 hh[4];
            #pragma unroll
            for (int jp = 0; jp < 4; jp++) {
                float2 f = *reinterpret_cast<float2*>(&acc[i][jp]);
                hh[jp] = __floats2half2_rn(f.x, f.y);
            }
            *(uint2*)&g_fth[(size_t)r * 64 + (tx << 2) + 0] = *(uint2*)&hh[0];
            *(uint2*)&g_fth[(size_t)r * 64 + (tx << 2) + 2] = *(uint2*)&hh[2];
        }
    }
}

// ---------------------------------------------------------------------------
// K5: atomic-free aggregation — QUARTER-WARP PER EDGE.
// fp16 rows are 256B = 8 lanes x 32B (two uint4 per lane), so one warp
// processes 4 edges per iteration: lane octet o takes edge t+o. Each lane
// holds 16 features (16*(lane&7)..+15) = half of head (lane&7)/2, so the
// per-head dot reduction is ONE xor-1 shuffle (vs 2 in R14, 3 in R8).
// The 16-FMA dot is split into 4 partial chains for short FMA depth.
// acc/s are merged across the 4 octets once per node (xor-8, xor-16).
// Max-subtraction skipped: mathematically identical softmax; |p*scale| <~ 7.
// ---------------------------------------------------------------------------
__global__ void agg_kernel(float* __restrict__ out, int N) {
    const int node = (blockIdx.x * blockDim.x + threadIdx.x) >> 5;
    if (node >= N) return;
    const int lane  = threadIdx.x & 31;
    const int hl    = lane & 7;       // position within octet (feature chunk)
    const int eslot = lane >> 3;      // 0..3: which edge of each group of 4

    const int start = g_off[node];
    const int deg   = g_cnt[node];

    // dst row chunk: features 16*hl .. 16*hl+15, fp32
    float b[16];
    #pragma unroll
    for (int q = 0; q < 4; q++) {
        float4 bv = *(const float4*)&g_ft[(size_t)node * HD + (hl << 4) + (q << 2)];
        b[q * 4 + 0] = bv.x; b[q * 4 + 1] = bv.y;
        b[q * 4 + 2] = bv.z; b[q * 4 + 3] = bv.w;
    }

    float acc[16];
    #pragma unroll
    for (int i = 0; i < 16; i++) acc[i] = 0.0f;
    float s = 0.0f;
    const float scale = 0.17677669529663687f;  // 1/sqrt(32)

    const uint4* fth4 = (const uint4*)g_fth;   // 16 uint4 per row

    for (int base = 0; base < deg; base += 32) {
        int j = base + lane;
        int sj = (j < deg) ? g_csr_src[start + j] : 0;
        int cnt = min(32, deg - base);

        // prologue: this octet's first edge (t=0 -> edge eslot)
        int sn = __shfl_sync(0xffffffffu, sj, min(eslot, 31));
        uint4 r0 = fth4[(size_t)sn * 16 + (hl << 1) + 0];
        uint4 r1 = fth4[(size_t)sn * 16 + (hl << 1) + 1];

        #pragma unroll 1
        for (int t = 0; t < cnt; t += 4) {
            uint4 c0 = r0, c1 = r1;
            bool valid = (t + eslot) < cnt;

            // prefetch next group's edge (uniform-shape shuffle, clamped idx)
            int nxt = t + 4 + eslot;
            int snn = __shfl_sync(0xffffffffu, sj, min(nxt, 31));
            if (nxt < cnt) {
                r0 = fth4[(size_t)snn * 16 + (hl << 1) + 0];
                r1 = fth4[(size_t)snn * 16 + (hl << 1) + 1];
            }

            // convert 16 halves -> 16 floats
            float f[16];
            {
                float2 t0 = __half22float2(*reinterpret_cast<__half2*>(&c0.x));
                float2 t1 = __half22float2(*reinterpret_cast<__half2*>(&c0.y));
                float2 t2 = __half22float2(*reinterpret_cast<__half2*>(&c0.z));
                float2 t3 = __half22float2(*reinterpret_cast<__half2*>(&c0.w));
                f[0] = t0.x; f[1] = t0.y; f[2] = t1.x; f[3] = t1.y;
                f[4] = t2.x; f[5] = t2.y; f[6] = t3.x; f[7] = t3.y;
                t0 = __half22float2(*reinterpret_cast<__half2*>(&c1.x));
                t1 = __half22float2(*reinterpret_cast<__half2*>(&c1.y));
                t2 = __half22float2(*reinterpret_cast<__half2*>(&c1.z));
                t3 = __half22float2(*reinterpret_cast<__half2*>(&c1.w));
                f[8] = t0.x;  f[9] = t0.y;  f[10] = t1.x; f[11] = t1.y;
                f[12] = t2.x; f[13] = t2.y; f[14] = t3.x; f[15] = t3.y;
            }

            // dot with dst chunk: 4 partial chains (FMA depth 4, then 3 adds)
            float p0 = f[0] * b[0], p1 = f[1] * b[1], p2 = f[2] * b[2], p3 = f[3] * b[3];
            #pragma unroll
            for (int q = 4; q < 16; q += 4) {
                p0 += f[q + 0] * b[q + 0];
                p1 += f[q + 1] * b[q + 1];
                p2 += f[q + 2] * b[q + 2];
                p3 += f[q + 3] * b[q + 3];
            }
            float p = (p0 + p1) + (p2 + p3);
            // partner lane (xor-1) holds the other half of this head
            p += __shfl_xor_sync(0xffffffffu, p, 1);

            float e = valid ? __expf(p * scale) : 0.0f;
            s += e;
            #pragma unroll
            for (int i = 0; i < 16; i++) acc[i] += e * f[i];
        }
    }

    // merge the four octets (same features, disjoint edge subsets)
    #pragma unroll
    for (int i = 0; i < 16; i++) {
        acc[i] += __shfl_xor_sync(0xffffffffu, acc[i], 8);
        acc[i] += __shfl_xor_sync(0xffffffffu, acc[i], 16);
    }
    s += __shfl_xor_sync(0xffffffffu, s, 8);
    s += __shfl_xor_sync(0xffffffffu, s, 16);

    float inv = (deg > 0) ? (1.0f / s) : 0.0f;
    // each lane writes one distinct float4: octet e writes quarter e of its
    // feature chunk -> 32 lanes cover the full 512B row, single wavefront.
    float4 v = make_float4(acc[(eslot << 2) + 0] * inv, acc[(eslot << 2) + 1] * inv,
                           acc[(eslot << 2) + 2] * inv, acc[(eslot << 2) + 3] * inv);
    *(float4*)&out[(size_t)node * HD + (hl << 4) + (eslot << 2)] = v;
}

// ---------------------------------------------------------------------------
extern "C" void kernel_launch(void* const* d_in, const int* in_sizes, int n_in,
                              void* d_out, int out_size) {
    const float* feat = (const float*)d_in[0];
    const float* W    = (const float*)d_in[1];
    const int*   src  = (const int*)d_in[2];
    const int*   dst  = (const int*)d_in[3];
    float* out = (float*)d_out;

    const int N = in_sizes[0] / IN_FEATS;   // 50000
    const int E = in_sizes[2];              // 800000
    const int nb = (N + SCAN_B - 1) / SCAN_B;

    static cudaStream_t s_gemm = nullptr;
    static cudaEvent_t  ev_fork = nullptr, ev_join = nullptr;
    static int* cnt_ptr = nullptr;
    if (s_gemm == nullptr) {
        cudaStreamCreateWithFlags(&s_gemm, cudaStreamNonBlocking);
        cudaEventCreateWithFlags(&ev_fork, cudaEventDisableTiming);
        cudaEventCreateWithFlags(&ev_join, cudaEventDisableTiming);
        cudaGetSymbolAddress((void**)&cnt_ptr, g_cnt);
    }

    // ---- fork: GEMM branch issued FIRST (R8 order — measured best) ----
    cudaEventRecord(ev_fork, 0);
    cudaStreamWaitEvent(s_gemm, ev_fork, 0);
    gemm_kernel<<<(N + GM - 1) / GM, 256, 0, s_gemm>>>(feat, W, N);
    cudaEventRecord(ev_join, s_gemm);

    // ---- main stream: CSR build branch (depends only on src, dst) ----
    cudaMemsetAsync(cnt_ptr, 0, (size_t)N * sizeof(int));
    hist_kernel<<<(E + 255) / 256, 256>>>(dst, E);
    scan_phase1<<<nb, SCAN_B>>>(N);
    scan_phase3<<<nb, SCAN_B>>>(N);
    scatter_kernel<<<(E + 255) / 256, 256>>>(src, dst, E);

    // ---- join, then aggregate ----
    cudaStreamWaitEvent(0, ev_join, 0);
    {
        int warps_per_block = 8;  // 256 threads
        int blocks = (N + warps_per_block - 1) / warps_per_block;
        agg_kernel<<<blocks, 256>>>(out, N);
    }
}